// round 17
// baseline (speedup 1.0000x reference)
#include <cuda_runtime.h>
#include <cuda_bf16.h>
#include <cstdint>

#define H4   4096
#define Bb   16
#define TPB  256
#define NCH  8                 // chunks of 64 k-rows (block K = 512)
#define RS   3                 // TMA ring slots
#define RAW_SLOT 32768         // 64 rows x 512 B fp32
#define WT_BASE  98304         // bf16 weights [k][col], pitch 136 bf16
#define WT_PITCH 272           // bytes (128 cols + 8 pad)
#define WT_SPLIT 17408         // 64 rows x 272
#define WT_BUF   34816         // hi + lo
#define ACT_BASE 167936        // bf16 acts [b][k], pitch 520 bf16
#define ACT_SPLIT 16640
#define ACT_PITCH 1040         // bytes
#define MB_BASE  201216
#define SMEM_NEED 201280

// scratch: 4 planes [mat*2+kc][16 b][4096] pre-activation partials (1 MB)
__device__ float g_part[4 * Bb * H4];
__device__ int   g_cnt[8];     // per-n-chunk arrival counters (self-resetting)

__device__ __forceinline__ uint32_t smem_u32(const void* p) {
    uint32_t a;
    asm("{ .reg .u64 t; cvta.to.shared.u64 t, %1; cvt.u32.u64 %0, t; }"
        : "=r"(a) : "l"(p));
    return a;
}
__device__ __forceinline__ void mbar_init(uint32_t m, uint32_t c) {
    asm volatile("mbarrier.init.shared.b64 [%0], %1;" :: "r"(m), "r"(c) : "memory");
}
__device__ __forceinline__ void mbar_expect_tx(uint32_t m, uint32_t b) {
    asm volatile("mbarrier.arrive.expect_tx.shared.b64 _, [%0], %1;"
                 :: "r"(m), "r"(b) : "memory");
}
__device__ __forceinline__ void mbar_wait(uint32_t m, uint32_t ph) {
    asm volatile(
        "{\n\t.reg .pred P;\n\t"
        "W_%=:\n\t"
        "mbarrier.try_wait.parity.acquire.cta.shared::cta.b64 P, [%0], %1, 0x989680;\n\t"
        "@P bra D_%=;\n\t"
        "bra W_%=;\n\t"
        "D_%=:\n\t}"
        :: "r"(m), "r"(ph) : "memory");
}
__device__ __forceinline__ void bulk_copy(uint32_t dst, const void* src,
                                          uint32_t bytes, uint32_t m) {
    asm volatile(
        "cp.async.bulk.shared::cluster.global.mbarrier::complete_tx::bytes "
        "[%0], [%1], %2, [%3];"
        :: "r"(dst), "l"(src), "r"(bytes), "r"(m) : "memory");
}
__device__ __forceinline__ void mma_bf16(float* d, const uint32_t* a,
                                         uint32_t b0, uint32_t b1) {
    asm volatile(
        "mma.sync.aligned.m16n8k16.row.col.f32.bf16.bf16.f32 "
        "{%0,%1,%2,%3}, {%4,%5,%6,%7}, {%8,%9}, {%0,%1,%2,%3};"
        : "+f"(d[0]), "+f"(d[1]), "+f"(d[2]), "+f"(d[3])
        : "r"(a[0]), "r"(a[1]), "r"(a[2]), "r"(a[3]), "r"(b0), "r"(b1));
}
__device__ __forceinline__ void ldsm_x4(uint32_t* r, uint32_t addr) {
    asm volatile("ldmatrix.sync.aligned.m8n8.x4.shared.b16 {%0,%1,%2,%3}, [%4];"
        : "=r"(r[0]), "=r"(r[1]), "=r"(r[2]), "=r"(r[3]) : "r"(addr));
}
__device__ __forceinline__ void ldsm_x4_t(uint32_t* r, uint32_t addr) {
    asm volatile("ldmatrix.sync.aligned.m8n8.x4.trans.shared.b16 {%0,%1,%2,%3}, [%4];"
        : "=r"(r[0]), "=r"(r[1]), "=r"(r[2]), "=r"(r[3]) : "r"(addr));
}
__device__ __forceinline__ uint32_t bfpair(float a, float b) {
    __nv_bfloat162 t;
    t.x = __float2bfloat16_rn(a);
    t.y = __float2bfloat16_rn(b);
    return *reinterpret_cast<uint32_t*>(&t);
}

// ---------------------------------------------------------------------------
// Fused: split-bf16 tensor-core GEMM partials + counter-gated gates epilogue.
// grid = (32 jt, 2 kc, 2 mat) = 128 blocks, 256 threads.
// Per chunk (64 k): convert raw fp32 -> bf16 hi/lo [k][col] (float4 LDS +
// STS.64, conflict-free); 8 warps x 2 col-tiles x 3 split-MMAs per k16-step,
// fragments via ldmatrix.x4 (acts) / ldmatrix.x4.trans (weights).
// Last-arriving block per n-chunk reduces 4 planes + bias + LSTM gates.
// ---------------------------------------------------------------------------
__global__ __launch_bounds__(TPB, 1) void lstm_tc(
    const float* __restrict__ Wi,  const float* __restrict__ Wh,
    const float* __restrict__ x,   const float* __restrict__ h,
    const float* __restrict__ Wib, const float* __restrict__ Whb,
    const float* __restrict__ cin, float* __restrict__ out)
{
    extern __shared__ char sm[];
    const uint32_t base = smem_u32(sm);

    const int jt  = blockIdx.x;             // 0..31
    const int kc  = blockIdx.y;             // 0..1
    const int mat = blockIdx.z;             // 0: Wi/x, 1: Wh/h
    const float* __restrict__ W   = mat ? Wh : Wi;
    const float* __restrict__ act = mat ? h  : x;
    const int j0  = jt * 128;
    const int k0  = kc * 512;
    const int tid = threadIdx.x;
    const int w    = tid >> 5;
    const int lane = tid & 31;
    const int grp  = lane >> 2;
    const int tig  = lane & 3;

    const uint32_t mb[RS] = { base + MB_BASE, base + MB_BASE + 8, base + MB_BASE + 16 };

    if (tid == 0) {
        mbar_init(mb[0], 1); mbar_init(mb[1], 1); mbar_init(mb[2], 1);
        mbar_expect_tx(mb[0], RAW_SLOT);
        mbar_expect_tx(mb[1], RAW_SLOT);
        mbar_expect_tx(mb[2], RAW_SLOT);
    }
    __syncthreads();

    if (tid < 192) {                        // prologue TMA: chunks 0..2
        int c = tid >> 6, r = tid & 63;
        bulk_copy(base + c * RAW_SLOT + r * 512,
                  W + (size_t)(k0 + c * 64 + r) * H4 + j0, 512, mb[c]);
    }

    // convert activations -> [b][k] bf16 hi/lo (pitch 1040 B, conflict-free)
    {
        char* ah = sm + ACT_BASE;
        char* al = ah + ACT_SPLIT;
#pragma unroll
        for (int i = 0; i < 16; i++) {
            int id = i * TPB + tid;         // 4096 k-pairs
            int b  = id >> 8;
            int kp = id & 255;
            float2 v = *reinterpret_cast<const float2*>(act + b * 1024 + k0 + 2 * kp);
            float h0 = __bfloat162float(__float2bfloat16_rn(v.x));
            float h1 = __bfloat162float(__float2bfloat16_rn(v.y));
            uint32_t off = (uint32_t)(b * ACT_PITCH + 4 * kp);
            *reinterpret_cast<uint32_t*>(ah + off) = bfpair(v.x, v.y);
            *reinterpret_cast<uint32_t*>(al + off) = bfpair(v.x - h0, v.y - h1);
        }
    }

    // per-lane ldmatrix address components
    const int arow  = (lane & 7) + ((lane >> 3) & 1) * 8;      // act row (batch)
    const int akofs = (lane >> 4) * 8;                          // act k offset
    const uint32_t a_off = (uint32_t)(arow * ACT_PITCH + akofs * 2);
    const int bkrow = (lane & 7) + ((lane >> 3) & 1) * 8;      // weight k row
    const int bncol = w * 16 + (lane >> 4) * 8;                // weight col
    const uint32_t b_off = (uint32_t)(bkrow * WT_PITCH + bncol * 2);

    float d0[4] = {0.f, 0.f, 0.f, 0.f};
    float d1[4] = {0.f, 0.f, 0.f, 0.f};

#pragma unroll
    for (int c = 0; c < NCH; c++) {
        const int slot = c % RS;
        const int p    = c & 1;
        mbar_wait(mb[slot], (c / RS) & 1);

        // convert raw fp32 chunk -> Wt hi/lo [k][col] (no transpose)
        {
            char* raw = sm + slot * RAW_SLOT;
            char* wh_ = sm + WT_BASE + p * WT_BUF;
            char* wl_ = wh_ + WT_SPLIT;
#pragma unroll
            for (int i = 0; i < 8; i++) {
                int idx = i * TPB + tid;    // 2048 float4 groups
                int k  = idx >> 5;          // 0..63
                int c4 = idx & 31;          // x4 cols
                float4 v = *reinterpret_cast<const float4*>(raw + k * 512 + c4 * 16);
                float h0 = __bfloat162float(__float2bfloat16_rn(v.x));
                float h1 = __bfloat162float(__float2bfloat16_rn(v.y));
                float h2 = __bfloat162float(__float2bfloat16_rn(v.z));
                float h3 = __bfloat162float(__float2bfloat16_rn(v.w));
                uint32_t off = (uint32_t)(k * WT_PITCH + c4 * 8);
                *reinterpret_cast<uint2*>(wh_ + off) =
                    make_uint2(bfpair(v.x, v.y), bfpair(v.z, v.w));
                *reinterpret_cast<uint2*>(wl_ + off) =
                    make_uint2(bfpair(v.x - h0, v.y - h1), bfpair(v.z - h2, v.w - h3));
            }
        }
        if (tid == 0 && c + RS < NCH) mbar_expect_tx(mb[slot], RAW_SLOT);
        __syncthreads();
        if (c + RS < NCH && tid < 64)
            bulk_copy(base + slot * RAW_SLOT + tid * 512,
                      W + (size_t)(k0 + (c + RS) * 64 + tid) * H4 + j0, 512, mb[slot]);

        // compute: 4 k16-steps
        {
            const uint32_t wh_a = base + WT_BASE + p * WT_BUF + b_off;
            const uint32_t wl_a = wh_a + WT_SPLIT;
            const uint32_t ah_a = base + ACT_BASE + a_off + (uint32_t)(c * 64) * 2;
            const uint32_t al_a = ah_a + ACT_SPLIT;
#pragma unroll
            for (int ks = 0; ks < 4; ks++) {
                uint32_t ah[4], alo[4], bh[4], bl[4];
                ldsm_x4(ah,  ah_a + ks * 32);          // 16 k * 2B
                ldsm_x4(alo, al_a + ks * 32);
                ldsm_x4_t(bh, wh_a + ks * 16 * WT_PITCH);
                ldsm_x4_t(bl, wl_a + ks * 16 * WT_PITCH);
                mma_bf16(d0, ah,  bh[0], bh[1]);
                mma_bf16(d0, ah,  bl[0], bl[1]);
                mma_bf16(d0, alo, bh[0], bh[1]);
                mma_bf16(d1, ah,  bh[2], bh[3]);
                mma_bf16(d1, ah,  bl[2], bl[3]);
                mma_bf16(d1, alo, bh[2], bh[3]);
            }
        }
    }

    // store partials: D rows = batches grp/grp+8, cols within warp tile
    {
        float* gp = g_part + (size_t)(mat * 2 + kc) * Bb * H4;
        int c0 = j0 + w * 16 + tig * 2;
        *reinterpret_cast<float2*>(gp + (size_t)grp * H4 + c0) = make_float2(d0[0], d0[1]);
        *reinterpret_cast<float2*>(gp + (size_t)(grp + 8) * H4 + c0) = make_float2(d0[2], d0[3]);
        *reinterpret_cast<float2*>(gp + (size_t)grp * H4 + c0 + 8) = make_float2(d1[0], d1[1]);
        *reinterpret_cast<float2*>(gp + (size_t)(grp + 8) * H4 + c0 + 8) = make_float2(d1[2], d1[3]);
    }

    // ---- counter-gated epilogue: 16 producers per n-chunk (jt%8) ----
    __threadfence();
    __syncthreads();
    __shared__ int s_last;
    const int nc = jt & 7;
    if (tid == 0) {
        int old = atomicAdd(&g_cnt[nc], 1);
        s_last = (old == 15);
        if (old == 15) __threadfence();
    }
    __syncthreads();

    if (s_last) {
        const int b  = tid >> 4;            // 0..15
        const int n8 = (tid & 15) * 8;      // 8 consecutive n
        float pre[4][8];
#pragma unroll
        for (int g = 0; g < 4; g++) {
            int cb = g * 1024 + nc * 128 + n8;
            float4 s0 = *reinterpret_cast<const float4*>(Wib + cb);
            float4 s1 = *reinterpret_cast<const float4*>(Wib + cb + 4);
            float4 u0 = *reinterpret_cast<const float4*>(Whb + cb);
            float4 u1 = *reinterpret_cast<const float4*>(Whb + cb + 4);
            pre[g][0] = s0.x + u0.x; pre[g][1] = s0.y + u0.y;
            pre[g][2] = s0.z + u0.z; pre[g][3] = s0.w + u0.w;
            pre[g][4] = s1.x + u1.x; pre[g][5] = s1.y + u1.y;
            pre[g][6] = s1.z + u1.z; pre[g][7] = s1.w + u1.w;
        }
#pragma unroll
        for (int p = 0; p < 4; p++) {
            float4 t0[4], t1[4];
#pragma unroll
            for (int g = 0; g < 4; g++) {
                const float* gp = g_part + ((size_t)(p * Bb + b)) * H4
                                + g * 1024 + nc * 128 + n8;
                t0[g] = *reinterpret_cast<const float4*>(gp);
                t1[g] = *reinterpret_cast<const float4*>(gp + 4);
            }
#pragma unroll
            for (int g = 0; g < 4; g++) {
                pre[g][0] += t0[g].x; pre[g][1] += t0[g].y;
                pre[g][2] += t0[g].z; pre[g][3] += t0[g].w;
                pre[g][4] += t1[g].x; pre[g][5] += t1[g].y;
                pre[g][6] += t1[g].z; pre[g][7] += t1[g].w;
            }
        }
        const int o0 = b * 1024 + nc * 128 + n8;
        float4 c0 = *reinterpret_cast<const float4*>(cin + o0);
        float4 c1 = *reinterpret_cast<const float4*>(cin + o0 + 4);
        float cv[8] = {c0.x, c0.y, c0.z, c0.w, c1.x, c1.y, c1.z, c1.w};
        float hn[8], cn[8];
#pragma unroll
        for (int e = 0; e < 8; e++) {
            float ig = 1.0f / (1.0f + expf(-pre[0][e]));
            float fg = 1.0f / (1.0f + expf(-pre[1][e]));
            float gg = tanhf(pre[2][e]);
            float og = 1.0f / (1.0f + expf(-pre[3][e]));
            cn[e] = fg * cv[e] + ig * gg;
            hn[e] = og * tanhf(cn[e]);
        }
        *reinterpret_cast<float4*>(out + o0)     = make_float4(hn[0], hn[1], hn[2], hn[3]);
        *reinterpret_cast<float4*>(out + o0 + 4) = make_float4(hn[4], hn[5], hn[6], hn[7]);
        *reinterpret_cast<float4*>(out + Bb * 1024 + o0)     = make_float4(cn[0], cn[1], cn[2], cn[3]);
        *reinterpret_cast<float4*>(out + Bb * 1024 + o0 + 4) = make_float4(cn[4], cn[5], cn[6], cn[7]);
        if (tid == 0) atomicExch(&g_cnt[nc], 0);   // reset for graph replay
    }
}

// ---------------------------------------------------------------------------
// Inputs (metadata order): x, h, c, context, Wi, Wi_b, Wh, Wh_b, AZ_il, AZ_ir,
// AZ_hl, AZ_hr.  context / AZ_* are dead (multiplied by 0 in the reference).
// ---------------------------------------------------------------------------
extern "C" void kernel_launch(void* const* d_in, const int* in_sizes, int n_in,
                              void* d_out, int out_size)
{
    (void)in_sizes; (void)n_in; (void)out_size;
    const float* x   = (const float*)d_in[0];
    const float* h   = (const float*)d_in[1];
    const float* c   = (const float*)d_in[2];
    const float* Wi  = (const float*)d_in[4];
    const float* Wib = (const float*)d_in[5];
    const float* Wh  = (const float*)d_in[6];
    const float* Whb = (const float*)d_in[7];
    float* out = (float*)d_out;

    cudaFuncSetAttribute(lstm_tc,
                         cudaFuncAttributeMaxDynamicSharedMemorySize, SMEM_NEED);

    dim3 g(32, 2, 2);
    lstm_tc<<<g, TPB, SMEM_NEED>>>(Wi, Wh, x, h, Wib, Whb, c, out);
}